// round 17
// baseline (speedup 1.0000x reference)
#include <cuda_runtime.h>

// MinConv2d: 3x3 min-pool, stride 1, pad 1 (zero padding PARTICIPATES in min).
// Input/output: (8, 64, 512, 512) fp32 -> 512 planes of 512x512.
//
// R16: R3 structure (separable rolling min, batch-4 loads, direct L1-hit edge
// scalars, ROWS=32, 8192 blocks) with interior/edge tile specialization:
// interior tiles (14 of 16) run a branch-free loop with no row clamping and
// pure pointer-increment addressing.

#define PLANE_H 512
#define PLANE_W 512
#define ROWS_PER_BLOCK 32
#define THREADS 128   // 128 * 4 floats = 512 = full row width

__device__ __forceinline__ float4 fmin4(float4 a, float4 b) {
    return make_float4(fminf(a.x, b.x), fminf(a.y, b.y),
                       fminf(a.z, b.z), fminf(a.w, b.w));
}

__device__ __forceinline__ float4 hmin_row(float4 v, float l, float r) {
    float4 h;
    h.x = fminf(l,   fminf(v.x, v.y));
    h.y = fminf(v.x, fminf(v.y, v.z));
    h.z = fminf(v.y, fminf(v.z, v.w));
    h.w = fminf(v.z, fminf(v.w, r));
    return h;
}

template <bool EDGE>
__device__ __forceinline__ void run_tile(const float* __restrict__ xp,
                                         float* __restrict__ op,
                                         int y0, int base,
                                         bool hasL, bool hasR) {
    // ---- prologue: input rows y0-1 and y0 ----
    float4 h2, h1;
    {
        const int yi = y0 - 1;
        const int yc = EDGE ? (yi < 0 ? 0 : yi) : yi;
        const float* row = xp + (size_t)yc * PLANE_W + base;
        float4 v = *reinterpret_cast<const float4*>(row);
        float  l = hasL ? __ldg(row - 1) : 0.0f;
        float  r = hasR ? __ldg(row + 4) : 0.0f;
        h2 = hmin_row(v, l, r);
        if (EDGE && yi < 0) h2 = make_float4(0.f, 0.f, 0.f, 0.f);
    }
    {
        const float* row = xp + (size_t)y0 * PLANE_W + base;
        float4 v = *reinterpret_cast<const float4*>(row);
        float  l = hasL ? __ldg(row - 1) : 0.0f;
        float  r = hasR ? __ldg(row + 4) : 0.0f;
        h1 = hmin_row(v, l, r);
    }

    // ---- steady state: input rows y0+1 .. y0+32, batched 4 at a time ----
    const float* pin  = xp + (size_t)(y0 + 1) * PLANE_W + base;  // row y0+1
    float*       pout = op + (size_t)y0 * PLANE_W + base;        // row y0

    for (int r0 = 1; r0 <= ROWS_PER_BLOCK; r0 += 4) {
        float4 v[4];
        float  L[4], R[4];

        #pragma unroll
        for (int j = 0; j < 4; ++j) {
            const float* row = pin + (size_t)j * PLANE_W;
            if (EDGE) {
                // Last tile: row y0+r0+j may be 512 (the zero pad) -> clamp
                // the load to row 511 (legal), zero the result below.
                const int yi = y0 + r0 + j;
                row = xp + (size_t)(yi < PLANE_H ? yi : PLANE_H - 1) * PLANE_W + base;
            }
            v[j] = *reinterpret_cast<const float4*>(row);
            L[j] = hasL ? __ldg(row - 1) : 0.0f;
            R[j] = hasR ? __ldg(row + 4) : 0.0f;
        }

        #pragma unroll
        for (int j = 0; j < 4; ++j) {
            float4 h = hmin_row(v[j], L[j], R[j]);
            if (EDGE && (y0 + r0 + j) >= PLANE_H)
                h = make_float4(0.f, 0.f, 0.f, 0.f);
            *reinterpret_cast<float4*>(pout + (size_t)j * PLANE_W) =
                fmin4(h2, fmin4(h1, h));
            h2 = h1;
            h1 = h;
        }
        pin  += (size_t)4 * PLANE_W;
        pout += (size_t)4 * PLANE_W;
    }
}

__global__ __launch_bounds__(THREADS)
void minpool3x3_kernel(const float* __restrict__ x, float* __restrict__ out) {
    const int plane = blockIdx.y;
    const float* __restrict__ xp = x + (size_t)plane * PLANE_H * PLANE_W;
    float* __restrict__ op = out + (size_t)plane * PLANE_H * PLANE_W;

    const int base  = threadIdx.x * 4;
    const int y0    = blockIdx.x * ROWS_PER_BLOCK;
    const bool hasL = (base != 0);
    const bool hasR = (base + 4 != PLANE_W);

    const int last = (PLANE_H / ROWS_PER_BLOCK) - 1;
    if (blockIdx.x == 0 || blockIdx.x == (unsigned)last) {
        run_tile<true>(xp, op, y0, base, hasL, hasR);
    } else {
        run_tile<false>(xp, op, y0, base, hasL, hasR);
    }
}

extern "C" void kernel_launch(void* const* d_in, const int* in_sizes, int n_in,
                              void* d_out, int out_size) {
    const float* x = (const float*)d_in[0];
    float* out = (float*)d_out;

    const int planes = 8 * 64;                       // 512
    dim3 grid(PLANE_H / ROWS_PER_BLOCK, planes);     // (16, 512) = 8192 blocks
    dim3 block(THREADS);
    minpool3x3_kernel<<<grid, block>>>(x, out);
}